// round 7
// baseline (speedup 1.0000x reference)
#include <cuda_runtime.h>
#include <cstddef>

#define ALPHA_ 0.0001f
#define NN 16
#define TT 8
#define VV 256
#define FF 64
#define NVV (NN*VV*VV)
#define NBLK 256

__device__ float g_sloss[NBLK];
__device__ float g_fsum[NN * FF];
__device__ float g_sq[NN];
__device__ unsigned int g_counter = 0;

typedef unsigned long long u64;

__device__ __forceinline__ u64 fma2(u64 a, u64 b, u64 c) {
    u64 r;
    asm("fma.rn.f32x2 %0, %1, %2, %3;" : "=l"(r) : "l"(a), "l"(b), "l"(c));
    return r;
}
__device__ __forceinline__ float2 unpack2(u64 v) {
    float2 r;
    asm("mov.b64 {%0, %1}, %2;" : "=f"(r.x), "=f"(r.y) : "l"(v));
    return r;
}

// grid (16 jt, 16 n), 256 threads = 8 warps, 2 CTAs/SM (desynchronized).
// Block owns 16 j-columns x ALL 256 i-rows (softmax block-local).
// Warp w: i-band [32w, 32w+32). Lane: li=lane&7 (i), lj=lane>>3 (j).
// Thread tile: 4 i (li+8k) x 4 j (4m+lj). All operands stream from GMEM
// (L1-resident 64KB/n); no staging phase, no pre-main-loop barrier.
extern "C" __global__ void __launch_bounds__(256, 2)
fused_kernel(const float* __restrict__ x, const float* __restrict__ a,
             float* __restrict__ out) {
    __shared__ __align__(16) float sa[FF];
    __shared__ float red[256];
    __shared__ float part[8][16];
    __shared__ float invs[16];
    __shared__ float wsum[8];
    __shared__ unsigned int s_flag;

    const int tid  = threadIdx.x;
    const int lane = tid & 31;
    const int w    = tid >> 5;
    const int li   = lane & 7;
    const int lj   = lane >> 3;
    const int jt   = blockIdx.x;
    const int n    = blockIdx.y;
    const float* __restrict__ xm = x + (size_t)(n * TT + TT / 2) * (VV * FF);

    if (tid < FF) sa[tid] = a[tid];

    // dloss partials for this block's 16 rows [16jt, 16jt+16):
    // per-feature sums -> global atomics; sum of squares -> g_sq.
    {
        const int f  = tid & 63;
        const int rg = tid >> 6;
        const float* rp = xm + (jt * 16 + rg * 4) * FF + f;
        float v0 = rp[0], v1 = rp[FF], v2 = rp[2 * FF], v3 = rp[3 * FF];
        float Sq = v0 * v0 + v1 * v1 + v2 * v2 + v3 * v3;
        red[tid] = v0 + v1 + v2 + v3;
#pragma unroll
        for (int o = 16; o; o >>= 1) Sq += __shfl_down_sync(~0u, Sq, o);
        if (lane == 0) wsum[w] = Sq;
        __syncthreads();
        if (tid < FF) {
            float fs = red[tid] + red[tid + 64] + red[tid + 128] + red[tid + 192];
            atomicAdd(&g_fsum[n * FF + tid], fs);
        }
        if (tid == 0) {
            float sq = 0.f;
#pragma unroll
            for (int k = 0; k < 8; ++k) sq += wsum[k];
            atomicAdd(&g_sq[n], sq);
        }
    }

    const float* __restrict__ xib = xm + (w * 32 + li) * FF;   // +k*8*FF + h*4
    const float* __restrict__ xjb = xm + (jt * 16 + lj) * FF;  // +m*4*FF + h*4
    const u64 M    = 0x7fffffff7fffffffULL;
    const u64 NEG1 = 0xBF800000BF800000ULL;   // {-1.f, -1.f}

    u64 acc[16];
#pragma unroll
    for (int p = 0; p < 16; ++p) acc[p] = 0;

#pragma unroll 2
    for (int h = 0; h < 16; ++h) {
        ulonglong2 av = *reinterpret_cast<const ulonglong2*>(sa + h * 4);
        ulonglong2 xi[4], xj[4];
#pragma unroll
        for (int k = 0; k < 4; ++k)      // 8 distinct addrs/warp -> full wavefront
            xi[k] = *reinterpret_cast<const ulonglong2*>(xib + k * 8 * FF + h * 4);
#pragma unroll
        for (int m = 0; m < 4; ++m)      // 4 distinct addrs/warp
            xj[m] = *reinterpret_cast<const ulonglong2*>(xjb + m * 4 * FF + h * 4);
#pragma unroll
        for (int k = 0; k < 4; ++k)
#pragma unroll
            for (int m = 0; m < 4; ++m) {
                u64 d0 = fma2(xj[m].x, NEG1, xi[k].x) & M;   // |xi - xj|
                u64 d1 = fma2(xj[m].y, NEG1, xi[k].y) & M;
                u64 t  = fma2(d0, av.x, acc[k * 4 + m]);     // * a, accumulate
                acc[k * 4 + m] = fma2(d1, av.y, t);
            }
    }

    // exp (scores >= 0, relu is identity) + per-thread column partials.
    float e[16];
    float cp[4];
#pragma unroll
    for (int m = 0; m < 4; ++m) cp[m] = 0.f;
#pragma unroll
    for (int k = 0; k < 4; ++k)
#pragma unroll
        for (int m = 0; m < 4; ++m) {
            float2 u = unpack2(acc[k * 4 + m]);
            float v  = __expf(u.x + u.y);
            e[k * 4 + m] = v;
            cp[m] += v;
        }
    // Reduce over li (lanes within each 8-lane lj-group; only li==0 used).
#pragma unroll
    for (int o = 4; o; o >>= 1)
#pragma unroll
        for (int m = 0; m < 4; ++m) cp[m] += __shfl_down_sync(~0u, cp[m], o);
    if (li == 0)
#pragma unroll
        for (int m = 0; m < 4; ++m) part[w][4 * m + lj] = cp[m];
    __syncthreads();
    if (tid < 16) {
        float s = 0.f;
#pragma unroll
        for (int b = 0; b < 8; ++b) s += part[b][tid];
        invs[tid] = 1.0f / s;
    }
    __syncthreads();

    float iv[4];
#pragma unroll
    for (int m = 0; m < 4; ++m) iv[m] = invs[4 * m + lj];

    // Normalize, write S, accumulate S^2.
    float sq2 = 0.f;
    float* ob = out + (size_t)n * (VV * VV) + jt * 16 + lj;
#pragma unroll
    for (int k = 0; k < 4; ++k) {
        const size_t ro = (size_t)(w * 32 + li + 8 * k) * VV;
#pragma unroll
        for (int m = 0; m < 4; ++m) {
            float Sv = e[k * 4 + m] * iv[m];
            ob[ro + 4 * m] = Sv;
            sq2 = fmaf(Sv, Sv, sq2);
        }
    }
#pragma unroll
    for (int o = 16; o; o >>= 1) sq2 += __shfl_down_sync(~0u, sq2, o);
    if (lane == 0) wsum[w] = sq2;
    __syncthreads();

    // Last-block finalize (graph-safe: all accumulators reset every call).
    const int bid = n * 16 + jt;
    if (tid == 0) {
        float t = 0.f;
#pragma unroll
        for (int k = 0; k < 8; ++k) t += wsum[k];
        __stcg(&g_sloss[bid], t);
        __threadfence();
        unsigned int c = atomicAdd(&g_counter, 1u);
        s_flag = (c == NBLK - 1) ? 1u : 0u;
    }
    __syncthreads();
    if (s_flag && w == 0) {
        __threadfence();
        float s = 0.f;
#pragma unroll
        for (int k = 0; k < 8; ++k) s += __ldcg(&g_sloss[lane + (k << 5)]);
        float t1 = (lane < NN) ? __ldcg(&g_sq[lane]) : 0.f;
        float t2 = 0.f;
#pragma unroll
        for (int k = 0; k < 32; ++k) {
            float fv = __ldcg(&g_fsum[lane + (k << 5)]);
            t2 = fmaf(fv, fv, t2);
        }
#pragma unroll
        for (int o = 16; o; o >>= 1) {
            s  += __shfl_down_sync(~0u, s, o);
            t1 += __shfl_down_sync(~0u, t1, o);
            t2 += __shfl_down_sync(~0u, t2, o);
        }
        if (lane == 0) {
            out[NVV]     = s * (ALPHA_ / (float)NN);
            out[NVV + 1] = 2.f * ALPHA_ * ((float)VV * t1 - t2);
            g_counter = 0;
        }
        // Reset accumulators for the next graph replay.
        if (lane < NN) g_sq[lane] = 0.f;
#pragma unroll
        for (int k = 0; k < 32; ++k) g_fsum[lane + (k << 5)] = 0.f;
    }
}

extern "C" void kernel_launch(void* const* d_in, const int* in_sizes, int n_in,
                              void* d_out, int out_size) {
    const float* x = (const float*)d_in[0];
    const float* a = (const float*)d_in[1];
    if (n_in >= 2 && in_sizes[0] == FF) {      // defensive input-order check
        const float* t = x; x = a; a = t;
    }
    float* out = (float*)d_out;
    fused_kernel<<<dim3(16, NN), 256>>>(x, a, out);
}

// round 8
// speedup vs baseline: 1.3948x; 1.3948x over previous
#include <cuda_runtime.h>
#include <cstddef>

#define ALPHA_ 0.0001f
#define NN 16
#define TT 8
#define VV 256
#define FF 64
#define NVV (NN*VV*VV)
#define YS 68
#define NBLK 144            // 9 tile-groups x 16 n; <= 148 SMs, co-resident

__device__ float g_sloss[NBLK];
__device__ float g_dloss[NN];
__device__ float g_colsum[NN * VV];
__device__ unsigned int g_c1 = 0, g_c2 = 0, g_counter = 0;
__device__ volatile unsigned int g_r1 = 0, g_r2 = 0;

typedef unsigned long long u64;

__device__ __forceinline__ u64 addx2(u64 a, u64 b) {
    u64 r;
    asm("add.rn.f32x2 %0, %1, %2;" : "=l"(r) : "l"(a), "l"(b));
    return r;
}
__device__ __forceinline__ float2 unpack2(u64 v) {
    float2 r;
    asm("mov.b64 {%0, %1}, %2;" : "=f"(r.x), "=f"(r.y) : "l"(v));
    return r;
}

// Whole-grid spin barrier: safe because all 144 blocks are co-resident.
__device__ __forceinline__ void grid_barrier(unsigned int* cnt,
                                             volatile unsigned int* rel) {
    __syncthreads();
    if (threadIdx.x == 0) {
        __threadfence();
        if (atomicAdd(cnt, 1u) == NBLK - 1) {
            *rel = 1u;
        } else {
            while (*rel == 0u) __nanosleep(64);
        }
        __threadfence();
    }
    __syncthreads();
}

// grid (9, 16): block b of batch n computes 4 of the 36 upper-triangle
// 32x32 tiles of the symmetric exp(score) matrix (0.56x the pairs), writes
// E both orientations, atomically accumulates column sums; after a grid
// barrier it normalizes a 28/29-row stripe in place.
extern "C" __global__ void __launch_bounds__(512, 1)
fused_kernel(const float* __restrict__ x, const float* __restrict__ a,
             float* __restrict__ out) {
    extern __shared__ float y[];            // [256][YS] y = xm*a (~68KB)
    __shared__ float red[512];
    __shared__ float part[16][32];
    __shared__ float cspart[VV];            // block-local colsum partials
    __shared__ float invs[VV];
    __shared__ float tb[32][33];            // transpose buffer
    __shared__ float sqw[16];
    __shared__ unsigned int s_flag;

    const int tid  = threadIdx.x;
    const int lane = tid & 31;
    const int w    = tid >> 5;
    const int b    = blockIdx.x;            // 0..8
    const int n    = blockIdx.y;
    const float* __restrict__ xm = x + (size_t)(n * TT + TT / 2) * (VV * FF);
    float* __restrict__ on = out + (size_t)n * (VV * VV);

    // ---- Stage y = xm*a (fixed feature per thread -> free dloss raw sums).
    const int   f  = tid & 63;
    const float af = __ldg(&a[f]);
    float Sx = 0.f, Sq = 0.f;
#pragma unroll
    for (int k = 0; k < 32; ++k) {
        int idx = tid + (k << 9);
        float v = xm[idx];
        y[(idx >> 6) * YS + f] = v * af;
        Sx += v;
        Sq = fmaf(v, v, Sq);
    }
    red[tid] = Sx;
#pragma unroll
    for (int o = 16; o; o >>= 1) Sq += __shfl_down_sync(~0u, Sq, o);
    if (lane == 0) sqw[w] = Sq;
    if (tid < VV) cspart[tid] = 0.f;
    __syncthreads();

    // dloss_n = 2*(V*sum x^2 - sum_f (sum_i x)^2): S's column sums are
    // exactly 1, so sum(S@d2) == sum(d2). Block b==0 per n computes it.
    if (b == 0 && w == 0) {
        float s1 = 0.f, s2 = 0.f;
#pragma unroll
        for (int r = 0; r < 8; ++r) {
            s1 += red[lane + (r << 6)];
            s2 += red[lane + 32 + (r << 6)];
        }
        float t  = s1 * s1 + s2 * s2;
        float sq = (lane < 16) ? sqw[lane] : 0.f;
#pragma unroll
        for (int o = 16; o; o >>= 1) {
            t  += __shfl_down_sync(~0u, t, o);
            sq += __shfl_down_sync(~0u, sq, o);
        }
        if (lane == 0) __stcg(&g_dloss[n], 2.f * ((float)VV * sq - t));
    }

    // ---- Phase A: 4 upper-triangle tiles. Warp w -> tile rows 2w,2w+1;
    //      lane -> tile column.
    const u64 M   = 0x7fffffff7fffffffULL;
    const u64 SGN = 0x8000000080000000ULL;

#pragma unroll 1
    for (int t4 = 0; t4 < 4; ++t4) {
        int t = b * 4 + t4;
        int tt = t, r = 0;
        while (tt >= 8 - r) { tt -= 8 - r; ++r; }
        const int c = r + tt;                      // tile (r, c), r <= c

        // Column vector -y_j (lane-distinct .128 loads, 272B stride).
        u64 nxj[32];
        {
            const float* __restrict__ yc = y + (c * 32 + lane) * YS;
#pragma unroll
            for (int q = 0; q < 16; ++q) {
                ulonglong2 v = *reinterpret_cast<const ulonglong2*>(yc + q * 4);
                nxj[2 * q]     = v.x ^ SGN;
                nxj[2 * q + 1] = v.y ^ SGN;
            }
        }

        float e[2];
#pragma unroll
        for (int d = 0; d < 2; ++d) {
            const float* __restrict__ xi = y + (r * 32 + 2 * w + d) * YS;
            u64 a0 = 0, a1 = 0, a2 = 0, a3 = 0;
#pragma unroll
            for (int q = 0; q < 8; ++q) {
                ulonglong2 p0 = *reinterpret_cast<const ulonglong2*>(xi + q * 8);
                ulonglong2 p1 = *reinterpret_cast<const ulonglong2*>(xi + q * 8 + 4);
                a0 = addx2(a0, addx2(p0.x, nxj[4 * q])     & M);
                a1 = addx2(a1, addx2(p0.y, nxj[4 * q + 1]) & M);
                a2 = addx2(a2, addx2(p1.x, nxj[4 * q + 2]) & M);
                a3 = addx2(a3, addx2(p1.y, nxj[4 * q + 3]) & M);
            }
            float2 u = unpack2(addx2(addx2(a0, a1), addx2(a2, a3)));
            e[d] = __expf(u.x + u.y);              // scores >= 0: relu = id
        }

        // Direct E write (coalesced).
        {
            float* op = on + (size_t)(r * 32 + 2 * w) * VV + c * 32 + lane;
            __stcg(op, e[0]);
            __stcg(op + VV, e[1]);
        }
        // Column-partial for cols of c-tile.
        part[w][lane] = e[0] + e[1];
        // Row sums double as colsums of the mirrored tile (off-diag only).
        if (r != c) {
            float r0 = e[0], r1 = e[1];
#pragma unroll
            for (int o = 16; o; o >>= 1) {
                r0 += __shfl_down_sync(~0u, r0, o);
                r1 += __shfl_down_sync(~0u, r1, o);
            }
            if (lane == 0) {
                cspart[r * 32 + 2 * w]     += r0;
                cspart[r * 32 + 2 * w + 1] += r1;
            }
            tb[lane][2 * w]     = e[0];
            tb[lane][2 * w + 1] = e[1];
        }
        __syncthreads();
        if (tid < 32) {
            float s = 0.f;
#pragma unroll
            for (int ww = 0; ww < 16; ++ww) s += part[ww][tid];
            cspart[c * 32 + tid] += s;
        }
        if (r != c) {       // transposed E write (coalesced via smem)
            float* tp = on + (size_t)(c * 32 + 2 * w) * VV + r * 32 + lane;
            __stcg(tp,      tb[2 * w][lane]);
            __stcg(tp + VV, tb[2 * w + 1][lane]);
        }
        __syncthreads();
    }

    // Publish column-sum partials.
    if (tid < VV) atomicAdd(&g_colsum[n * VV + tid], cspart[tid]);

    // ---- Grid barrier 1: all E + colsums visible.
    grid_barrier(&g_c1, &g_r1);

    if (tid < VV) invs[tid] = 1.0f / __ldcg(&g_colsum[n * VV + tid]);

    // ---- Grid barrier 2: all blocks have read colsums -> safe to re-zero.
    grid_barrier(&g_c2, &g_r2);

    const int start = b * 28 + (b < 4 ? b : 4);
    const int cnt   = 28 + (b < 4 ? 1 : 0);
    if (tid < cnt) __stcg(&g_colsum[n * VV + start + tid], 0.f);  // for replay

    // ---- Phase C: normalize rows [start, start+cnt), accumulate S^2.
    __syncthreads();
    const int rofs = tid >> 8;              // 0..1
    const int col  = tid & 255;
    const float iv = invs[col];
    float sq2 = 0.f;
#pragma unroll 2
    for (int rr = 0; rr < 29; rr += 2) {
        int ro = rr + rofs;
        if (ro < cnt) {
            float* p = on + (size_t)(start + ro) * VV + col;
            float S = __ldcg(p) * iv;
            __stcg(p, S);
            sq2 = fmaf(S, S, sq2);
        }
    }
#pragma unroll
    for (int o = 16; o; o >>= 1) sq2 += __shfl_down_sync(~0u, sq2, o);
    if (lane == 0) sqw[w] = sq2;
    __syncthreads();

    // ---- Last-block finalize (graph-safe: all state reset each call).
    const int bid = n * 9 + b;
    if (tid == 0) {
        float t = 0.f;
#pragma unroll
        for (int k = 0; k < 16; ++k) t += sqw[k];
        __stcg(&g_sloss[bid], t);
        __threadfence();
        unsigned int cdone = atomicAdd(&g_counter, 1u);
        s_flag = (cdone == NBLK - 1) ? 1u : 0u;
    }
    __syncthreads();
    if (s_flag && w == 0) {
        __threadfence();
        float s = 0.f;
#pragma unroll
        for (int k = 0; k < 5; ++k) {
            int idx = lane + (k << 5);
            if (idx < NBLK) s += __ldcg(&g_sloss[idx]);
        }
        float dl = (lane < NN) ? __ldcg(&g_dloss[lane]) : 0.f;
#pragma unroll
        for (int o = 16; o; o >>= 1) {
            s  += __shfl_down_sync(~0u, s, o);
            dl += __shfl_down_sync(~0u, dl, o);
        }
        if (lane == 0) {
            out[NVV]     = s * (ALPHA_ / (float)NN);
            out[NVV + 1] = dl * ALPHA_;
            g_c1 = 0; g_r1 = 0; g_c2 = 0; g_r2 = 0;   // reset barrier state
            g_counter = 0;
        }
    }
}

extern "C" void kernel_launch(void* const* d_in, const int* in_sizes, int n_in,
                              void* d_out, int out_size) {
    const float* x = (const float*)d_in[0];
    const float* a = (const float*)d_in[1];
    if (n_in >= 2 && in_sizes[0] == FF) {      // defensive input-order check
        const float* t = x; x = a; a = t;
    }
    float* out = (float*)d_out;

    const int smem = VV * YS * (int)sizeof(float);
    cudaFuncSetAttribute(fused_kernel,
                         cudaFuncAttributeMaxDynamicSharedMemorySize, smem);
    fused_kernel<<<dim3(9, NN), 512, smem>>>(x, a, out);
}

// round 9
// speedup vs baseline: 1.7071x; 1.2239x over previous
#include <cuda_runtime.h>
#include <cstddef>

#define ALPHA_ 0.0001f
#define NN 16
#define TT 8
#define VV 256
#define FF 64
#define NVV (NN*VV*VV)
#define YS 68               // padded row stride: conflict-free column reads
#define NBLK 128

__device__ float g_sloss[NBLK];
__device__ float g_dloss[NN];
__device__ unsigned int g_counter = 0;

// grid (8 j-tiles, 16 n), 512 threads = 16 warps.
// Warp w handles i in [16w,16w+16); lane owns column j = jt*32 + lane.
// Max-trick core: sum_f |yi-yj| = 2*sum_f max(yi,yj) - Ti - Tj, with
// T = row sums of y precomputed. Inner loop = 1 FMNMX (alu) + 1 FADD (fma)
// per feature -> fma-pipe element work HALVED vs diff/abs/acc.
extern "C" __global__ void __launch_bounds__(512, 1)
fused_kernel(const float* __restrict__ x, const float* __restrict__ a,
             float* __restrict__ out) {
    extern __shared__ float y[];            // [256][YS] y = xm*a (~68KB)
    __shared__ float red[512];              // Sx partials, then colsum tree
    __shared__ float Ts[VV];                // row sums of y
    __shared__ float sqw[16];
    __shared__ float cs[32];
    __shared__ float wsum[16];

    const int tid  = threadIdx.x;
    const int lane = tid & 31;
    const int w    = tid >> 5;
    const int n    = blockIdx.y;
    const int jt   = blockIdx.x;
    const float* __restrict__ xm = x + (size_t)(n * TT + TT / 2) * (VV * FF);

    // Stage y = xm * a (tid&63 = fixed feature -> free per-f raw sums).
    const int   f  = tid & 63;
    const float af = __ldg(&a[f]);
    float Sx = 0.f, Sq = 0.f;
#pragma unroll
    for (int k = 0; k < 32; ++k) {
        int idx = tid + (k << 9);
        float v = xm[idx];
        y[(idx >> 6) * YS + f] = v * af;
        Sx += v;
        Sq = fmaf(v, v, Sq);
    }
    red[tid] = Sx;
#pragma unroll
    for (int o = 16; o; o >>= 1) Sq += __shfl_down_sync(~0u, Sq, o);
    if (lane == 0) sqw[w] = Sq;
    __syncthreads();

    // Row sums T_r (one-time; 4-way-conflict float4 reads, negligible).
    if (tid < VV) {
        const float4* p = reinterpret_cast<const float4*>(&y[tid * YS]);
        float s0 = 0.f, s1 = 0.f, s2 = 0.f, s3 = 0.f;
#pragma unroll
        for (int k = 0; k < 16; k += 4) {
            float4 v0 = p[k], v1 = p[k + 1], v2 = p[k + 2], v3 = p[k + 3];
            s0 += v0.x + v0.y + v0.z + v0.w;
            s1 += v1.x + v1.y + v1.z + v1.w;
            s2 += v2.x + v2.y + v2.z + v2.w;
            s3 += v3.x + v3.y + v3.z + v3.w;
        }
        Ts[tid] = (s0 + s1) + (s2 + s3);
    }

    // dloss_n = 2*(V*sum x^2 - sum_f (sum_i x)^2); valid because S's column
    // sums are exactly 1 (softmax axis) so sum(S@d2) == sum(d2).
    if (jt == 0 && w == 1) {
        float s1 = 0.f, s2 = 0.f;
#pragma unroll
        for (int r = 0; r < 8; ++r) {
            s1 += red[lane + (r << 6)];
            s2 += red[lane + 32 + (r << 6)];
        }
        float t  = s1 * s1 + s2 * s2;
        float sq = (lane < 16) ? sqw[lane] : 0.f;
#pragma unroll
        for (int o = 16; o; o >>= 1) {
            t  += __shfl_down_sync(~0u, t, o);
            sq += __shfl_down_sync(~0u, sq, o);
        }
        if (lane == 0) __stcg(&g_dloss[n], 2.f * ((float)VV * sq - t));
    }
    __syncthreads();

    // This thread's column in registers.
    const int j     = jt * 32 + lane;
    const int ibase = w << 4;
    float xj[FF];
    {
        const float4* xjp = reinterpret_cast<const float4*>(&y[j * YS]);
#pragma unroll
        for (int q = 0; q < 16; ++q) {
            float4 v = xjp[q];
            xj[4 * q]     = v.x;
            xj[4 * q + 1] = v.y;
            xj[4 * q + 2] = v.z;
            xj[4 * q + 3] = v.w;
        }
    }
    const float Tj = Ts[j];

    float tmp[16];
    float colpart = 0.f;
#pragma unroll
    for (int g = 0; g < 16; ++g) {
        const float4* __restrict__ xi =
            reinterpret_cast<const float4*>(&y[(ibase + g) * YS]);
        float a0 = 0.f, a1 = 0.f, a2 = 0.f, a3 = 0.f;
#pragma unroll
        for (int q = 0; q < 16; ++q) {
            float4 p = xi[q];                    // broadcast LDS.128
            a0 += fmaxf(p.x, xj[4 * q]);         // FMNMX (alu) + FADD (fma)
            a1 += fmaxf(p.y, xj[4 * q + 1]);
            a2 += fmaxf(p.z, xj[4 * q + 2]);
            a3 += fmaxf(p.w, xj[4 * q + 3]);
        }
        float s  = (a0 + a1) + (a2 + a3);
        float sc = 2.f * s - Ts[ibase + g] - Tj; // = sum_f |yi - yj| >= 0
        float e  = __expf(sc);                   // relu is identity
        tmp[g] = e;
        colpart += e;
    }

    // Column sums across the 16 warps (tree).
    __syncthreads();                 // red[] reuse barrier
    red[tid] = colpart;
    __syncthreads();
    if (tid < 32) {
        float s = 0.f;
#pragma unroll
        for (int ww = 0; ww < 16; ++ww) s += red[ww * 32 + tid];
        cs[tid] = s;
    }
    __syncthreads();
    const float inv = 1.0f / cs[lane];

    // Write S (coalesced) + accumulate S^2.
    float sq2 = 0.f;
    float* ocol = out + (size_t)n * (VV * VV) + jt * 32 + lane;
#pragma unroll
    for (int g = 0; g < 16; ++g) {
        float Sv = tmp[g] * inv;
        ocol[(size_t)(ibase + g) * VV] = Sv;
        sq2 = fmaf(Sv, Sv, sq2);
    }
#pragma unroll
    for (int o = 16; o; o >>= 1) sq2 += __shfl_down_sync(~0u, sq2, o);
    if (lane == 0) wsum[w] = sq2;
    __syncthreads();

    // Last-block finalize (graph-safe: counter reset each call).
    __shared__ unsigned int s_flag;
    const int bid = n * 8 + jt;
    if (tid == 0) {
        float t = 0.f;
#pragma unroll
        for (int k = 0; k < 16; ++k) t += wsum[k];
        __stcg(&g_sloss[bid], t);
        __threadfence();
        unsigned int c = atomicAdd(&g_counter, 1u);
        s_flag = (c == NBLK - 1) ? 1u : 0u;
    }
    __syncthreads();
    if (s_flag && w == 0) {
        __threadfence();
        float s = 0.f;
#pragma unroll
        for (int k = 0; k < 4; ++k) s += __ldcg(&g_sloss[lane + (k << 5)]);
        float dl = (lane < NN) ? __ldcg(&g_dloss[lane]) : 0.f;
#pragma unroll
        for (int o = 16; o; o >>= 1) {
            s  += __shfl_down_sync(~0u, s, o);
            dl += __shfl_down_sync(~0u, dl, o);
        }
        if (lane == 0) {
            out[NVV]     = s * (ALPHA_ / (float)NN);
            out[NVV + 1] = dl * ALPHA_;
            g_counter = 0;
        }
    }
}

extern "C" void kernel_launch(void* const* d_in, const int* in_sizes, int n_in,
                              void* d_out, int out_size) {
    const float* x = (const float*)d_in[0];
    const float* a = (const float*)d_in[1];
    if (n_in >= 2 && in_sizes[0] == FF) {      // defensive input-order check
        const float* t = x; x = a; a = t;
    }
    float* out = (float*)d_out;

    const int smem = VV * YS * (int)sizeof(float);
    cudaFuncSetAttribute(fused_kernel,
                         cudaFuncAttributeMaxDynamicSharedMemorySize, smem);
    fused_kernel<<<dim3(8, NN), 512, smem>>>(x, a, out);
}